// round 9
// baseline (speedup 1.0000x reference)
#include <cuda_runtime.h>

#define HH 128
#define WW 48
#define HW 6144            // 128*48
#define NSPLIT 3
#define MLEN 1920          // 5760 / 3 (split-KV)
#define LOG2E_HALF 0.72134752044448170f   // 0.5*log2(e)

typedef unsigned long long ull;

// ---------------- scratch (device globals) ----------------
__device__ float g_qs[32 * HW];          // q conv output, pre-scaled
__device__ float g_kp[32 * 144 * 64];    // flange-padded k (flat, pad stays 0)
__device__ float g_vp[32 * 144 * 64];    // flange-padded v
__device__ float g_wqkv[3 * 576 * 32];   // repacked [t][pos][co]
__device__ float g_wo[288 * 64];         // repacked [pos][co]
__device__ float g_pnum[NSPLIT * 16 * 4 * 3072];  // partial numerators [s][n][c][q]
__device__ float g_pden[NSPLIT * 16 * 3072];      // partial denominators [s][n][q]

// ---------------- packed f32x2 helpers ----------------
__device__ __forceinline__ ull pk2(float a, float b) {
    ull r; asm("mov.b64 %0,{%1,%2};" : "=l"(r) : "f"(a), "f"(b)); return r;
}
__device__ __forceinline__ void upk2(float& a, float& b, ull v) {
    asm("mov.b64 {%0,%1},%2;" : "=f"(a), "=f"(b) : "l"(v));
}
__device__ __forceinline__ ull fma2(ull a, ull b, ull c) {
    ull d; asm("fma.rn.f32x2 %0,%1,%2,%3;" : "=l"(d) : "l"(a), "l"(b), "l"(c)); return d;
}
__device__ __forceinline__ ull add2(ull a, ull b) {
    ull d; asm("add.rn.f32x2 %0,%1,%2;" : "=l"(d) : "l"(a), "l"(b)); return d;
}
__device__ __forceinline__ ull mul2(ull a, ull b) {
    ull d; asm("mul.rn.f32x2 %0,%1,%2;" : "=l"(d) : "l"(a), "l"(b)); return d;
}
__device__ __forceinline__ float ex2f(float x) {
    float y; asm("ex2.approx.f32 %0, %1;" : "=f"(y) : "f"(x)); return y;
}
__device__ __forceinline__ float rcpf(float x) {
    float y; asm("rcp.approx.f32 %0, %1;" : "=f"(y) : "f"(x)); return y;
}

// ---------------- weight repack ----------------
__global__ void repack_kernel(const float* __restrict__ wq, const float* __restrict__ wk,
                              const float* __restrict__ wv, const float* __restrict__ wo)
{
    int i = blockIdx.x * blockDim.x + threadIdx.x;
    if (i < 3 * 18432) {
        int t = i / 18432, r = i % 18432;
        int pos = r >> 5, co = r & 31;
        const float* w = (t == 0) ? wq : (t == 1) ? wk : wv;
        g_wqkv[i] = w[co * 576 + pos];
    } else if (i < 3 * 18432 + 18432) {
        int r = i - 3 * 18432;
        int pos = r >> 6, co = r & 63;
        g_wo[r] = wo[co * 288 + pos];
    }
}

// ---------------- QKV conv3x3 (64 -> 32), z = t*2 + co-half -------------------------
// 256 threads: 128 pixels x 2 co-groups of 8. Same smem, half the per-thread chain.
__global__ __launch_bounds__(256) void conv_qkv_kernel(
    const float* __restrict__ x,
    const float* __restrict__ bq, const float* __restrict__ bk, const float* __restrict__ bv)
{
    extern __shared__ float sm[];
    float* sx = sm;               // 64*10*18 = 11520 floats
    float* sw = sm + 11520;       // 576*16   = 9216 floats
    const int t = blockIdx.z >> 1, half = blockIdx.z & 1;
    const int y0 = blockIdx.y * 8, x0 = blockIdx.x * 16;
    const int tid = threadIdx.x;

    for (int idx = tid; idx < 11520; idx += 256) {
        int ci = idx / 180, rem = idx % 180;
        int ry = rem / 18, rx = rem % 18;
        int gy = y0 + ry - 1, gx = x0 + rx - 1;
        float v = 0.f;
        if (gy >= 0 && gy < HH && gx >= 0 && gx < WW) v = x[ci * HW + gy * WW + gx];
        sx[idx] = v;
    }
    {
        const float* wsrc = g_wqkv + t * 18432 + half * 16;
        for (int idx = tid; idx < 2304; idx += 256) {
            int pos = idx >> 2, q = idx & 3;
            float4 w4 = *(const float4*)(wsrc + pos * 32 + q * 4);
            *(float4*)&sw[pos * 16 + q * 4] = w4;
        }
    }
    __syncthreads();

    const int p = tid & 127, grp = tid >> 7;          // pixel, co-group of 8
    const int ty = p >> 4, tx = p & 15;
    const int cobase = half * 16 + grp * 8;
    const float* bias = (t == 0) ? bq : (t == 1) ? bk : bv;
    ull acc2[4];
    #pragma unroll
    for (int c = 0; c < 4; c++) acc2[c] = pk2(bias[cobase + 2*c], bias[cobase + 2*c + 1]);

    for (int ci = 0; ci < 64; ci++) {
        #pragma unroll
        for (int ky = 0; ky < 3; ky++) {
            #pragma unroll
            for (int kx = 0; kx < 3; kx++) {
                float xv = sx[(ci * 10 + ty + ky) * 18 + tx + kx];
                ull xv2 = pk2(xv, xv);
                const ulonglong2* wr = (const ulonglong2*)&sw[(ci * 9 + ky * 3 + kx) * 16 + grp * 8];
                ulonglong2 w0 = wr[0];
                ulonglong2 w1 = wr[1];
                acc2[0] = fma2(xv2, w0.x, acc2[0]);
                acc2[1] = fma2(xv2, w0.y, acc2[1]);
                acc2[2] = fma2(xv2, w1.x, acc2[2]);
                acc2[3] = fma2(xv2, w1.y, acc2[3]);
            }
        }
    }
    const int y = y0 + ty, xx = x0 + tx;
    float av[8];
    #pragma unroll
    for (int c = 0; c < 4; c++) upk2(av[2*c], av[2*c+1], acc2[c]);
    if (t == 0) {
        #pragma unroll
        for (int c = 0; c < 8; c++)
            g_qs[(cobase + c) * HW + y * WW + xx] = av[c] * LOG2E_HALF;
    } else {
        float* dst = (t == 1) ? g_kp : g_vp;
        #pragma unroll
        for (int c = 0; c < 8; c++)
            dst[((cobase + c) * 144 + y + 8) * 64 + (xx + 8)] = av[c];
    }
}

// ---------------- block-local attention, 3-way split-KV, MUFU ex2, 256 thr ----------
// grid (6 q-chunks, 16 blocks, 3 kv-thirds); 256 threads x 2 queries = 512 q/CTA.
// smem: component-sliced third-K/V: 8 * 1920 floats = 61440 bytes -> 3 CTAs/SM,
// 24 warps/SM = 6 warps/SMSP for rt-3 banked FFMA2 stall coverage.
__global__ __launch_bounds__(256, 3) void attn_kernel()
{
    extern __shared__ float sk[];
    const int n = blockIdx.y;
    const int s = blockIdx.z;
    const int h = n >> 1, j = n & 1;
    const int tid = threadIdx.x;

    // Stage one third of the flanged K/V (exact as_strided flat map):
    // flat = h*24576 + d*6144 + (s*48 + row)*48 + j*24 + m1
    {
        const int kbase = h * 24576 + j * 24 + s * 2304;
        for (int it = tid; it < MLEN; it += 256) {            // 4 comps * 48 rows * 10 vec4
            int c = it / 480, rem = it % 480;
            int row = rem / 10, v4 = rem % 10;
            int m = row * 40 + v4 * 4;
            int g = kbase + c * 6144 + row * 48 + v4 * 4;
            *(float4*)&sk[c * MLEN + m]          = *(const float4*)&g_kp[g];
            *(float4*)&sk[4*MLEN + c * MLEN + m] = *(const float4*)&g_vp[g];
        }
    }
    __syncthreads();

    const int qA = blockIdx.x * 512 + tid;
    const int qB = qA + 256;
    const int yA = qA / 24, xA = qA - yA * 24;
    const int yB = qB / 24, xB = qB - yB * 24;
    const int aA = yA * WW + j * 24 + xA;
    const int aB = yB * WW + j * 24 + xB;
    const int cb = h * 4 * HW;

    const ull qa0 = pk2(g_qs[cb + aA],        g_qs[cb + aA]);
    const ull qa1 = pk2(g_qs[cb + HW + aA],   g_qs[cb + HW + aA]);
    const ull qa2 = pk2(g_qs[cb + 2*HW + aA], g_qs[cb + 2*HW + aA]);
    const ull qa3 = pk2(g_qs[cb + 3*HW + aA], g_qs[cb + 3*HW + aA]);
    const ull qb0 = pk2(g_qs[cb + aB],        g_qs[cb + aB]);
    const ull qb1 = pk2(g_qs[cb + HW + aB],   g_qs[cb + HW + aB]);
    const ull qb2 = pk2(g_qs[cb + 2*HW + aB], g_qs[cb + 2*HW + aB]);
    const ull qb3 = pk2(g_qs[cb + 3*HW + aB], g_qs[cb + 3*HW + aB]);

    ull denA = 0, aAx = 0, aAy = 0, aAz = 0, aAw = 0;
    ull denB = 0, aBx = 0, aBy = 0, aBz = 0, aBw = 0;

    // 9 FFMA2 on the FMA pipe + 2 ex2 on MUFU per qstep (2 kv elements, 1 query)
    auto qstep = [&](ull q0, ull q1, ull q2, ull q3,
                     ull kx, ull ky, ull kz, ull kw,
                     ull vx, ull vy, ull vz, ull vw,
                     ull& den, ull& ax, ull& ay, ull& az, ull& aw)
    {
        ull s2 = fma2(q3, kw, fma2(q2, kz, fma2(q1, ky, mul2(q0, kx))));
        float sl, sh;
        upk2(sl, sh, s2);                 // free (register-pair aliasing)
        float el = ex2f(sl);              // MUFU
        float eh = ex2f(sh);              // MUFU
        ull e2 = pk2(el, eh);             // free
        den = add2(den, e2);
        ax = fma2(e2, vx, ax); ay = fma2(e2, vy, ay);
        az = fma2(e2, vz, az); aw = fma2(e2, vw, aw);
    };

    const float* skx = sk;
    const float* sky = sk + MLEN;
    const float* skz = sk + 2*MLEN;
    const float* skw = sk + 3*MLEN;
    const float* svx = sk + 4*MLEN;
    const float* svy = sk + 5*MLEN;
    const float* svz = sk + 6*MLEN;
    const float* svw = sk + 7*MLEN;

    for (int m = 0; m < MLEN; m += 4) {
        ulonglong2 kx = *(const ulonglong2*)(skx + m);
        ulonglong2 ky = *(const ulonglong2*)(sky + m);
        ulonglong2 kz = *(const ulonglong2*)(skz + m);
        ulonglong2 kw = *(const ulonglong2*)(skw + m);
        ulonglong2 vx = *(const ulonglong2*)(svx + m);
        ulonglong2 vy = *(const ulonglong2*)(svy + m);
        ulonglong2 vz = *(const ulonglong2*)(svz + m);
        ulonglong2 vw = *(const ulonglong2*)(svw + m);
        qstep(qa0,qa1,qa2,qa3, kx.x,ky.x,kz.x,kw.x, vx.x,vy.x,vz.x,vw.x, denA,aAx,aAy,aAz,aAw);
        qstep(qa0,qa1,qa2,qa3, kx.y,ky.y,kz.y,kw.y, vx.y,vy.y,vz.y,vw.y, denA,aAx,aAy,aAz,aAw);
        qstep(qb0,qb1,qb2,qb3, kx.x,ky.x,kz.x,kw.x, vx.x,vy.x,vz.x,vw.x, denB,aBx,aBy,aBz,aBw);
        qstep(qb0,qb1,qb2,qb3, kx.y,ky.y,kz.y,kw.y, vx.y,vy.y,vz.y,vw.y, denB,aBx,aBy,aBz,aBw);
    }

    float lo, hi;
    const int pbase = (s * 16 + n) * 4 * 3072;
    const int dbase = (s * 16 + n) * 3072;
    upk2(lo, hi, denA); g_pden[dbase + qA] = lo + hi;
    upk2(lo, hi, denB); g_pden[dbase + qB] = lo + hi;
    upk2(lo, hi, aAx); g_pnum[pbase + qA]          = lo + hi;
    upk2(lo, hi, aAy); g_pnum[pbase + 3072 + qA]   = lo + hi;
    upk2(lo, hi, aAz); g_pnum[pbase + 6144 + qA]   = lo + hi;
    upk2(lo, hi, aAw); g_pnum[pbase + 9216 + qA]   = lo + hi;
    upk2(lo, hi, aBx); g_pnum[pbase + qB]          = lo + hi;
    upk2(lo, hi, aBy); g_pnum[pbase + 3072 + qB]   = lo + hi;
    upk2(lo, hi, aBz); g_pnum[pbase + 6144 + qB]   = lo + hi;
    upk2(lo, hi, aBw); g_pnum[pbase + 9216 + qB]   = lo + hi;
}

// ---------------- output conv3x3 (32 -> 64), fused split-KV combine -----------------
// 256 threads: 128 pixels x 2 co-groups of 8; z = co quarter (16 co per CTA).
// Staging computes o = (sum_s num) / (sum_s den) directly from partials (no g_o).
__global__ __launch_bounds__(256) void conv_out_kernel(float* __restrict__ out)
{
    extern __shared__ float sm[];
    float* sx = sm;               // 32*10*18 = 5760 floats
    float* sw = sm + 5760;        // 288*16   = 4608 floats
    const int z  = blockIdx.z;
    const int y0 = blockIdx.y * 8, x0 = blockIdx.x * 16;
    const int tid = threadIdx.x;

    for (int idx = tid; idx < 5760; idx += 256) {
        int ci = idx / 180, rem = idx % 180;
        int ry = rem / 18, rx = rem % 18;
        int gy = y0 + ry - 1, gx = x0 + rx - 1;
        float v = 0.f;
        if (gy >= 0 && gy < HH && gx >= 0 && gx < WW) {
            int hh = ci >> 2, d = ci & 3;
            int jj = (gx >= 24) ? 1 : 0;
            int q = gy * 24 + (gx - jj * 24);
            int nn = hh * 2 + jj;
            float den = g_pden[nn * 3072 + q]
                      + g_pden[(16 + nn) * 3072 + q]
                      + g_pden[(32 + nn) * 3072 + q];
            float num = g_pnum[(nn * 4 + d) * 3072 + q]
                      + g_pnum[((16 + nn) * 4 + d) * 3072 + q]
                      + g_pnum[((32 + nn) * 4 + d) * 3072 + q];
            v = num * rcpf(den);
        }
        sx[idx] = v;
    }
    for (int idx = tid; idx < 1152; idx += 256) {
        int pos = idx >> 2, q = idx & 3;
        float4 w4 = *(const float4*)(g_wo + pos * 64 + z * 16 + q * 4);
        *(float4*)&sw[pos * 16 + q * 4] = w4;
    }
    __syncthreads();

    const int p = tid & 127, grp = tid >> 7;
    const int ty = p >> 4, tx = p & 15;
    ull acc2[4];
    #pragma unroll
    for (int c = 0; c < 4; c++) acc2[c] = 0;

    for (int ci = 0; ci < 32; ci++) {
        #pragma unroll
        for (int ky = 0; ky < 3; ky++) {
            #pragma unroll
            for (int kx = 0; kx < 3; kx++) {
                float xv = sx[(ci * 10 + ty + ky) * 18 + tx + kx];
                ull xv2 = pk2(xv, xv);
                const ulonglong2* wr = (const ulonglong2*)&sw[(ci * 9 + ky * 3 + kx) * 16 + grp * 8];
                ulonglong2 w0 = wr[0];
                ulonglong2 w1 = wr[1];
                acc2[0] = fma2(xv2, w0.x, acc2[0]);
                acc2[1] = fma2(xv2, w0.y, acc2[1]);
                acc2[2] = fma2(xv2, w1.x, acc2[2]);
                acc2[3] = fma2(xv2, w1.y, acc2[3]);
            }
        }
    }
    const int y = y0 + ty, xx = x0 + tx;
    float av[8];
    #pragma unroll
    for (int c = 0; c < 4; c++) upk2(av[2*c], av[2*c+1], acc2[c]);
    #pragma unroll
    for (int c = 0; c < 8; c++)
        out[(z * 16 + grp * 8 + c) * HW + y * WW + xx] = av[c];
}

// ---------------- launch ----------------
extern "C" void kernel_launch(void* const* d_in, const int* in_sizes, int n_in,
                              void* d_out, int out_size)
{
    const float* x  = (const float*)d_in[0];
    const float* wq = (const float*)d_in[1];
    const float* bq = (const float*)d_in[2];
    const float* wk = (const float*)d_in[3];
    const float* bk = (const float*)d_in[4];
    const float* wv = (const float*)d_in[5];
    const float* bv = (const float*)d_in[6];
    const float* wo = (const float*)d_in[7];
    float* out = (float*)d_out;

    cudaFuncSetAttribute(conv_qkv_kernel, cudaFuncAttributeMaxDynamicSharedMemorySize, 82944);
    cudaFuncSetAttribute(attn_kernel,     cudaFuncAttributeMaxDynamicSharedMemorySize, 61440);
    cudaFuncSetAttribute(conv_out_kernel, cudaFuncAttributeMaxDynamicSharedMemorySize, 41472);

    repack_kernel<<<(73728 + 255) / 256, 256>>>(wq, wk, wv, wo);
    conv_qkv_kernel<<<dim3(3, 16, 6), 256, 82944>>>(x, bq, bk, bv);
    attn_kernel<<<dim3(6, 16, 3), 256, 61440>>>();
    conv_out_kernel<<<dim3(3, 16, 4), 256, 41472>>>(out);
}